// round 15
// baseline (speedup 1.0000x reference)
#include <cuda_runtime.h>
#include <cuda_fp16.h>
#include <cstdint>

#define NBATCH 4
#define SEQ    4096
#define HID    2048
#define NE     64
#define NTOK   (NBATCH * SEQ)   // 16384
#define TTILE  128
#define NCHUNK (HID / 32)       // 64
#define CT     36               // tensor chunks: k in [0, 1152)
#define CF     28               // fma chunks:    k in [1152, 2048)
#define KBF    (CT * 32)        // 1152
#define TAU    1e-3f
#define WSCALE 64.0f
#define RSCALE (1.0f / 64.0f)

// dynamic smem (uint32 units):
//  [0,2048) Ah | [2048,4096) Al | [4096,5120) Bh | [5120,6144) Bl   (HMMA, 24KB)
//  [6144,10304)  xs   32*130 f32 (FFMA2 A)
//  [10304,12352) wsn  32*64  f32
//  [12352,14400) wss  32*64  f32
//  logits overlay L: 128*65 f32 = [0,8320)  (after both mainloops)
#define DSM_BYTES (14400 * 4)

typedef unsigned long long ull;

__device__ uint32_t g_wbh[NCHUNK * 1024];   // w*64 hi fp16x2, fragment layout
__device__ uint32_t g_wbl[NCHUNK * 1024];   // w*64 lo fp16x2
__device__ float g_wt [HID * NE];           // w^T [k][e]
__device__ float g_wts[HID * NE];           // w^T pair-swapped [k][e^1]
__device__ float g_ssum[NBATCH * NE];
__device__ int   g_cnt [NBATCH * NE];

__device__ __forceinline__ void mma16(float* d, const uint32_t* a, const uint32_t* b) {
    asm volatile(
        "mma.sync.aligned.m16n8k16.row.col.f32.f16.f16.f32 "
        "{%0,%1,%2,%3}, {%4,%5,%6,%7}, {%8,%9}, {%0,%1,%2,%3};"
        : "+f"(d[0]), "+f"(d[1]), "+f"(d[2]), "+f"(d[3])
        : "r"(a[0]), "r"(a[1]), "r"(a[2]), "r"(a[3]), "r"(b[0]), "r"(b[1]));
}
__device__ __forceinline__ uint32_t hilo_pack(float v0, float v1, uint32_t& lo) {
    __half h0 = __float2half_rn(v0), h1 = __float2half_rn(v1);
    __half l0 = __float2half_rn(v0 - __half2float(h0));
    __half l1 = __float2half_rn(v1 - __half2float(h1));
    __half2 H = __halves2half2(h0, h1), L = __halves2half2(l0, l1);
    lo = *(uint32_t*)&L;
    return *(uint32_t*)&H;
}
__device__ __forceinline__ ull pack2(float lo, float hi) {
    ull r; asm("mov.b64 %0, {%1, %2};" : "=l"(r) : "f"(lo), "f"(hi)); return r;
}
__device__ __forceinline__ void unpack2(ull v, float &lo, float &hi) {
    asm("mov.b64 {%0, %1}, %2;" : "=f"(lo), "=f"(hi) : "l"(v));
}
__device__ __forceinline__ void fma2(ull &d, ull a, ull b) {
    asm("fma.rn.f32x2 %0, %1, %2, %0;" : "+l"(d) : "l"(a), "l"(b));
}
#define BAR1() asm volatile("bar.sync 1, 256;" ::: "memory")
#define BAR2() asm volatile("bar.sync 2, 128;" ::: "memory")

// prep: fp16 frags (all chunks) + transposed f32 w (all k) + zero accumulators
__global__ void wprep_kernel(const float* __restrict__ w) {
    const int t = blockIdx.x;                    // chunk 0..63
    const int tid = threadIdx.x;
    if (t == 0 && tid < NBATCH * NE) { g_ssum[tid] = 0.0f; g_cnt[tid] = 0; }
    #pragma unroll
    for (int it = 0; it < 4; it++) {
        const int idx = tid + it * 256;
        const int r = idx & 1, l = (idx >> 1) & 31, fB = idx >> 6;
        const int nt = fB & 7, ks = fB >> 3;
        const int e = nt * 8 + (l >> 2);
        const int k = t * 32 + ks * 16 + ((l & 3) + r * 4) * 2;
        const float v0 = w[(size_t)e * HID + k]     * WSCALE;
        const float v1 = w[(size_t)e * HID + k + 1] * WSCALE;
        uint32_t lo;
        const uint32_t hi = hilo_pack(v0, v1, lo);
        g_wbh[t * 1024 + idx] = hi;
        g_wbl[t * 1024 + idx] = lo;
    }
    #pragma unroll
    for (int it = 0; it < 8; it++) {
        const int idx = tid + it * 256;          // 0..2047
        const int k = t * 32 + (idx >> 6), e = idx & 63;
        const float v = w[(size_t)e * HID + k];
        g_wt [(size_t)k * NE + e]       = v;
        g_wts[(size_t)k * NE + (e ^ 1)] = v;
    }
}

extern __shared__ uint32_t dsmu[];

__global__ __launch_bounds__(384, 1)
void gate_kernel(const float* __restrict__ x, const float* __restrict__ w,
                 float* __restrict__ out)
{
    const int tid = threadIdx.x;
    const int lane = tid & 31, wid = tid >> 5;
    const int tok0 = blockIdx.x * TTILE;

    __shared__ int   cnt_s[NE];
    __shared__ float psum[256];
    __shared__ float rzs[128];
    __shared__ int   cand[128][4];
    __shared__ float evx[128][4];
    if (tid < NE) cnt_s[tid] = 0;

    uint32_t* Ah = dsmu;
    uint32_t* Al = dsmu + 2048;
    uint32_t* Bh = dsmu + 4096;
    uint32_t* Bl = dsmu + 5120;
    float* xs  = (float*)(dsmu + 6144);
    float* wsn = (float*)(dsmu + 10304);
    float* wss = (float*)(dsmu + 12352);

    float acc[8][4];
    ull facc[4][4], facd[4][4];

    if (wid < 8) {
        // ============ tensor group: fp16x3 HMMA over k [0, KBF) ============
        #pragma unroll
        for (int nt = 0; nt < 8; nt++)
            #pragma unroll
            for (int r = 0; r < 4; r++) acc[nt][r] = 0.0f;

        const int stok = tid >> 1, skh = tid & 1;
        const float* xrow = x + (size_t)(tok0 + stok) * HID + skh * 16;
        const int ri = stok & 15, mt = stok >> 4;
        const int fA_s = skh * 8 + mt;
        const int rbase = (ri >= 8) ? 1 : 0;
        const int lbase = (ri & 7) * 4;

        float4 xr[4];
        uint4  bph, bpl;
        #pragma unroll
        for (int i = 0; i < 4; i++) xr[i] = *(const float4*)(xrow + i * 4);
        bph = *(const uint4*)(g_wbh + tid * 4);
        bpl = *(const uint4*)(g_wbl + tid * 4);

        for (int t = 0; t < CT; t++) {
            #pragma unroll
            for (int i = 0; i < 4; i++) {
                const float v[4] = {xr[i].x, xr[i].y, xr[i].z, xr[i].w};
                #pragma unroll
                for (int jj = 0; jj < 2; jj++) {
                    const int p = i * 2 + jj;
                    uint32_t lo;
                    const uint32_t hi = hilo_pack(v[jj * 2], v[jj * 2 + 1], lo);
                    const int reg = rbase + ((p >= 4) ? 2 : 0);
                    const int ad  = fA_s * 128 + (lbase + (p & 3)) * 4 + reg;
                    Ah[ad] = hi;
                    Al[ad] = lo;
                }
            }
            ((uint4*)Bh)[tid] = bph;
            ((uint4*)Bl)[tid] = bpl;
            BAR1();
            if (t + 1 < CT) {
                #pragma unroll
                for (int i = 0; i < 4; i++)
                    xr[i] = *(const float4*)(xrow + (t + 1) * 32 + i * 4);
                bph = *(const uint4*)(g_wbh + (t + 1) * 1024 + tid * 4);
                bpl = *(const uint4*)(g_wbl + (t + 1) * 1024 + tid * 4);
            }
            #pragma unroll
            for (int ks = 0; ks < 2; ks++) {
                const int fA = ks * 8 + wid;
                const uint4 AHv = *(const uint4*)(Ah + fA * 128 + lane * 4);
                const uint4 ALv = *(const uint4*)(Al + fA * 128 + lane * 4);
                uint2 BHv[8], BLv[8];
                #pragma unroll
                for (int nt = 0; nt < 8; nt++) {
                    const int fB = ks * 8 + nt;
                    BHv[nt] = *(const uint2*)(Bh + fB * 64 + lane * 2);
                    BLv[nt] = *(const uint2*)(Bl + fB * 64 + lane * 2);
                }
                #pragma unroll
                for (int nt = 0; nt < 8; nt++) mma16(acc[nt], &AHv.x, &BHv[nt].x);
                #pragma unroll
                for (int nt = 0; nt < 8; nt++) mma16(acc[nt], &AHv.x, &BLv[nt].x);
                #pragma unroll
                for (int nt = 0; nt < 8; nt++) mma16(acc[nt], &ALv.x, &BHv[nt].x);
            }
            BAR1();
        }
    } else {
        // ============ fma group: exact FFMA2 over k [KBF, 2048) ============
        const int ftid = tid - 256;               // 0..127
        const int m = ftid & 15;
        const int e_base = (ftid >> 4) * 8;
        #pragma unroll
        for (int q = 0; q < 4; q++)
            #pragma unroll
            for (int j = 0; j < 4; j++) { facc[q][j] = 0ull; facd[q][j] = 0ull; }

        for (int t = 0; t < CF; t++) {
            const int kb = KBF + t * 32;
            BAR2();
            #pragma unroll
            for (int it = 0; it < 8; it++) {
                const int idx = ftid + it * 128;
                const int tok = idx >> 3, c = idx & 7;
                const float4 v = *(const float4*)(x + (size_t)(tok0 + tok) * HID + kb + c * 4);
                xs[(c * 4 + 0) * 130 + tok] = v.x;
                xs[(c * 4 + 1) * 130 + tok] = v.y;
                xs[(c * 4 + 2) * 130 + tok] = v.z;
                xs[(c * 4 + 3) * 130 + tok] = v.w;
            }
            #pragma unroll
            for (int it = 0; it < 4; it++) {
                const int idx = ftid + it * 128;
                const int row = idx >> 4, c4 = idx & 15;
                *(float4*)(wsn + row * 64 + c4 * 4) =
                    *(const float4*)(g_wt  + (size_t)(kb + row) * NE + c4 * 4);
                *(float4*)(wss + row * 64 + c4 * 4) =
                    *(const float4*)(g_wts + (size_t)(kb + row) * NE + c4 * 4);
            }
            BAR2();
            #pragma unroll 4
            for (int kk = 0; kk < 32; kk++) {
                const float* wr = wsn + kk * 64 + e_base;
                const float* sr = wss + kk * 64 + e_base;
                const ulonglong2 Bn01 = *(const ulonglong2*)(wr);
                const ulonglong2 Bn23 = *(const ulonglong2*)(wr + 4);
                const ulonglong2 Bs01 = *(const ulonglong2*)(sr);
                const ulonglong2 Bs23 = *(const ulonglong2*)(sr + 4);
                #pragma unroll
                for (int q = 0; q < 4; q++) {
                    const ull A = *(const ull*)(xs + kk * 130 + q * 32 + m * 2);
                    fma2(facc[q][0], A, Bn01.x); fma2(facd[q][0], A, Bs01.x);
                    fma2(facc[q][1], A, Bn01.y); fma2(facd[q][1], A, Bs01.y);
                    fma2(facc[q][2], A, Bn23.x); fma2(facd[q][2], A, Bs23.x);
                    fma2(facc[q][3], A, Bn23.y); fma2(facd[q][3], A, Bs23.y);
                }
            }
        }
    }
    __syncthreads();

    // ---- tensor group writes logits (rescaled), pitch 65 ----
    float* L = (float*)dsmu;
    if (wid < 8) {
        const int row0 = wid * 16 + (lane >> 2);
        const int ec = (lane & 3) * 2;
        #pragma unroll
        for (int nt = 0; nt < 8; nt++) {
            const int e0 = nt * 8 + ec;
            L[row0 * 65 + e0]           = acc[nt][0] * RSCALE;
            L[row0 * 65 + e0 + 1]       = acc[nt][1] * RSCALE;
            L[(row0 + 8) * 65 + e0]     = acc[nt][2] * RSCALE;
            L[(row0 + 8) * 65 + e0 + 1] = acc[nt][3] * RSCALE;
        }
    }
    __syncthreads();

    // ---- fma group adds its exact partial ----
    if (wid >= 8) {
        const int ftid = tid - 256;
        const int m = ftid & 15;
        const int e_base = (ftid >> 4) * 8;
        #pragma unroll
        for (int q = 0; q < 4; q++) {
            const int t0 = q * 32 + m * 2;
            #pragma unroll
            for (int j = 0; j < 4; j++) {
                float alo, ahi, dlo, dhi;
                unpack2(facc[q][j], alo, ahi);
                unpack2(facd[q][j], dlo, dhi);
                const int e0 = e_base + 2 * j;
                L[t0 * 65 + e0]           += alo;
                L[(t0 + 1) * 65 + e0 + 1] += ahi;
                L[t0 * 65 + e0 + 1]       += dlo;
                L[(t0 + 1) * 65 + e0]     += dhi;
            }
        }
    }
    __syncthreads();

    // ---- per-token: top-4 scan, flag ambiguity, softmax (threads 0..127) ----
    float tv[4] = {-1e30f, -1e30f, -1e30f, -1e30f};
    int   tix[4] = {0, 0, 0, 0};
    bool  flag = false;
    if (tid < 128) {
        for (int e = 0; e < NE; e++) {
            const float Le = L[tid * 65 + e];
            if (Le > tv[3]) {
                int p = 3;
                while (p > 0 && Le > tv[p - 1]) {
                    tv[p] = tv[p - 1]; tix[p] = tix[p - 1]; p--;
                }
                tv[p] = Le; tix[p] = e;
            }
        }
        flag = (tv[0] - tv[1] < TAU) || (tv[1] - tv[2] < TAU);
        #pragma unroll
        for (int c = 0; c < 4; c++) cand[tid][c] = tix[c];

        float Z = 0.0f;
        const float mx = tv[0];
        #pragma unroll 8
        for (int e = 0; e < NE; e++) {
            const float pe = __expf(L[tid * 65 + e] - mx);
            Z += pe;
            L[tid * 65 + e] = pe;
        }
        rzs[tid] = 1.0f / Z;
    }
    __syncthreads();

    // ---- warp-cooperative exact fp32 recompute of flagged tokens ----
    if (wid < 4) {
        unsigned mask = __ballot_sync(0xffffffffu, flag);
        while (mask) {
            const int b = __ffs(mask) - 1; mask &= mask - 1;
            const int tk = wid * 32 + b;
            const float* xg = x + (size_t)(tok0 + tk) * HID;
            const int c0 = cand[tk][0], c1 = cand[tk][1],
                      c2 = cand[tk][2], c3 = cand[tk][3];
            float s0 = 0.f, s1 = 0.f, s2 = 0.f, s3 = 0.f;
            for (int k0 = lane * 4; k0 < HID; k0 += 128) {
                const float4 xa = *(const float4*)(xg + k0);
                const float4 w0 = *(const float4*)(w + (size_t)c0 * HID + k0);
                const float4 w1 = *(const float4*)(w + (size_t)c1 * HID + k0);
                const float4 w2 = *(const float4*)(w + (size_t)c2 * HID + k0);
                const float4 w3 = *(const float4*)(w + (size_t)c3 * HID + k0);
                s0 += xa.x*w0.x + xa.y*w0.y + xa.z*w0.z + xa.w*w0.w;
                s1 += xa.x*w1.x + xa.y*w1.y + xa.z*w1.z + xa.w*w1.w;
                s2 += xa.x*w2.x + xa.y*w2.y + xa.z*w2.z + xa.w*w2.w;
                s3 += xa.x*w3.x + xa.y*w3.y + xa.z*w3.z + xa.w*w3.w;
            }
            #pragma unroll
            for (int o = 16; o; o >>= 1) {
                s0 += __shfl_xor_sync(0xffffffffu, s0, o);
                s1 += __shfl_xor_sync(0xffffffffu, s1, o);
                s2 += __shfl_xor_sync(0xffffffffu, s2, o);
                s3 += __shfl_xor_sync(0xffffffffu, s3, o);
            }
            if (lane == 0) {
                evx[tk][0] = s0; evx[tk][1] = s1; evx[tk][2] = s2; evx[tk][3] = s3;
            }
        }
    }
    __syncthreads();

    // ---- finalize outputs (threads 0..127) ----
    if (tid < 128) {
        float ev[4];
        #pragma unroll
        for (int c = 0; c < 4; c++) ev[c] = flag ? evx[tid][c] : tv[c];

        int b1 = 0;
        #pragma unroll
        for (int c = 1; c < 4; c++)
            if (ev[c] > ev[b1] || (ev[c] == ev[b1] && tix[c] < tix[b1])) b1 = c;
        int b2 = (b1 == 0) ? 1 : 0;
        #pragma unroll
        for (int c = 0; c < 4; c++) {
            if (c == b1 || c == b2) continue;
            if (ev[c] > ev[b2] || (ev[c] == ev[b2] && tix[c] < tix[b2])) b2 = c;
        }

        const int gt = tok0 + tid;
        out[2 * gt + 0] = (float)tix[b1];
        out[2 * gt + 1] = (float)tix[b2];
        const float r = expf(ev[b2] - ev[b1]);
        const float inv = 1.0f / (1.0f + r);
        out[2 * NTOK + 2 * gt + 0] = inv;
        out[2 * NTOK + 2 * gt + 1] = r * inv;
        atomicAdd(&cnt_s[tix[b1]], 1);
        atomicAdd(&cnt_s[tix[b2]], 1);
    }
    __syncthreads();

    // ---- per-expert normalized-prob sums (threads 0..255) ----
    if (tid < 256) {
        const int e = tid & 63, h = tid >> 6;
        float s = 0.0f;
        #pragma unroll 8
        for (int r2 = h * 32; r2 < h * 32 + 32; r2++) s += L[r2 * 65 + e] * rzs[r2];
        psum[tid] = s;
    }
    __syncthreads();
    if (tid < NE) {
        const int b = tok0 >> 12;
        atomicAdd(&g_ssum[b * NE + tid],
                  psum[tid] + psum[64 + tid] + psum[128 + tid] + psum[192 + tid]);
        atomicAdd(&g_cnt[b * NE + tid], cnt_s[tid]);
    }
}

__global__ void aux_kernel(float* __restrict__ out) {
    int t = threadIdx.x;  // 256 = NBATCH*NE
    float v = ((float)g_cnt[t] * ((float)NE / (float)(SEQ * 2))) *
              (g_ssum[t] / (float)SEQ);
    #pragma unroll
    for (int o = 16; o; o >>= 1) v += __shfl_xor_sync(0xffffffffu, v, o);
    __shared__ float wsum[8];
    if ((t & 31) == 0) wsum[t >> 5] = v;
    __syncthreads();
    if (t < 8) {
        float s = wsum[t];
        #pragma unroll
        for (int o = 4; o; o >>= 1) s += __shfl_xor_sync(0xffu, s, o);
        if (t == 0) out[4 * NTOK] = 0.01f * s / (float)NBATCH;
    }
}

extern "C" void kernel_launch(void* const* d_in, const int* in_sizes, int n_in,
                              void* d_out, int out_size) {
    const float* x = (const float*)d_in[0];
    const float* w = (const float*)d_in[1];
    float* out = (float*)d_out;

    static int configured = 0;
    if (!configured) {
        cudaFuncSetAttribute(gate_kernel, cudaFuncAttributeMaxDynamicSharedMemorySize, DSM_BYTES);
        configured = 1;
    }
    wprep_kernel<<<NCHUNK, 256>>>(w);
    gate_kernel<<<NTOK / TTILE, 384, DSM_BYTES>>>(x, w, out);
    aux_kernel<<<1, 256>>>(out);
}

// round 16
// speedup vs baseline: 1.1911x; 1.1911x over previous
#include <cuda_runtime.h>
#include <cuda_fp16.h>
#include <cstdint>

#define NBATCH 4
#define SEQ    4096
#define HID    2048
#define NE     64
#define NTOK   (NBATCH * SEQ)   // 16384
#define TTILE  128
#define KC     32
#define NCHUNK (HID / KC)       // 64
#define TAU    1e-3f
#define WSCALE 64.0f
#define RSCALE (1.0f / 64.0f)

// dynamic smem (uint32 units): Ah[2048] Al[2048] Bh[1024] = 20KB
// logits overlay needs 128*65 floats = 33280B -> DSM = 33280
#define OFF_AH 0
#define OFF_AL 2048
#define OFF_BH 4096
#define DSM_BYTES 33280

__device__ uint32_t g_wbh[NCHUNK * 1024];   // w*64 hi fp16x2, fragment layout
__device__ float g_ssum[NBATCH * NE];
__device__ int   g_cnt [NBATCH * NE];

__device__ __forceinline__ void mma16(float* d, const uint32_t* a, const uint32_t* b) {
    asm volatile(
        "mma.sync.aligned.m16n8k16.row.col.f32.f16.f16.f32 "
        "{%0,%1,%2,%3}, {%4,%5,%6,%7}, {%8,%9}, {%0,%1,%2,%3};"
        : "+f"(d[0]), "+f"(d[1]), "+f"(d[2]), "+f"(d[3])
        : "r"(a[0]), "r"(a[1]), "r"(a[2]), "r"(a[3]), "r"(b[0]), "r"(b[1]));
}
__device__ __forceinline__ uint32_t hilo_pack(float v0, float v1, uint32_t& lo) {
    __half h0 = __float2half_rn(v0), h1 = __float2half_rn(v1);
    __half l0 = __float2half_rn(v0 - __half2float(h0));
    __half l1 = __float2half_rn(v1 - __half2float(h1));
    __half2 H = __halves2half2(h0, h1), L = __halves2half2(l0, l1);
    lo = *(uint32_t*)&L;
    return *(uint32_t*)&H;
}
__device__ __forceinline__ uint32_t hi_pack(float v0, float v1) {
    __half2 H = __halves2half2(__float2half_rn(v0), __float2half_rn(v1));
    return *(uint32_t*)&H;
}

// precompute w*64 hi fp16x2 in fragment layout; entry idx (0..1023) of chunk t:
// r = idx&1, l = (idx>>1)&31, fB = idx>>6 (= ks*8+nt)
// e = nt*8 + (l>>2); k = t*32 + ks*16 + ((l&3) + r*4)*2 + {0,1}
__global__ void wprep_kernel(const float* __restrict__ w) {
    const int t = blockIdx.x;
    if (t == 0 && threadIdx.x < NBATCH * NE) {
        g_ssum[threadIdx.x] = 0.0f; g_cnt[threadIdx.x] = 0;
    }
    #pragma unroll
    for (int it = 0; it < 4; it++) {
        const int idx = threadIdx.x + it * 256;
        const int r = idx & 1, l = (idx >> 1) & 31, fB = idx >> 6;
        const int nt = fB & 7, ks = fB >> 3;
        const int e = nt * 8 + (l >> 2);
        const int k = t * 32 + ks * 16 + ((l & 3) + r * 4) * 2;
        const float v0 = w[(size_t)e * HID + k]     * WSCALE;
        const float v1 = w[(size_t)e * HID + k + 1] * WSCALE;
        g_wbh[t * 1024 + idx] = hi_pack(v0, v1);
    }
}

extern __shared__ uint32_t dsmu[];

__global__ __launch_bounds__(256, 1)
void gate_kernel(const float* __restrict__ x, const float* __restrict__ w,
                 float* __restrict__ out)
{
    const int tid = threadIdx.x;
    const int lane = tid & 31, warp = tid >> 5;
    const int tok0 = blockIdx.x * TTILE;

    __shared__ int   cnt_s[NE];
    __shared__ float psum[256];
    __shared__ float rzs[128];
    __shared__ int   cand[128][4];
    __shared__ float evx[128][4];
    if (tid < NE) cnt_s[tid] = 0;

    uint32_t* Ah = dsmu + OFF_AH;
    uint32_t* Al = dsmu + OFF_AL;
    uint32_t* Bh = dsmu + OFF_BH;

    float acc[8][4];
    #pragma unroll
    for (int nt = 0; nt < 8; nt++)
        #pragma unroll
        for (int r = 0; r < 4; r++) acc[nt][r] = 0.0f;

    // A staging: thread owns token stok, k-half skh (16 k per chunk)
    const int stok = tid >> 1, skh = tid & 1;
    const float* xrow = x + (size_t)(tok0 + stok) * HID + skh * 16;
    const int ri = stok & 15, mt = stok >> 4;
    const int fA_s = skh * 8 + mt;
    const int rbase = (ri >= 8) ? 1 : 0;
    const int lbase = (ri & 7) * 4;

    float4 xr[4];
    uint4  bph;
    #pragma unroll
    for (int i = 0; i < 4; i++) xr[i] = *(const float4*)(xrow + i * 4);
    bph = *(const uint4*)(g_wbh + tid * 4);

    for (int t = 0; t < NCHUNK; t++) {
        // ---- stage A (fp16 hi/lo pairs into fragment layout) ----
        #pragma unroll
        for (int i = 0; i < 4; i++) {
            const float v[4] = {xr[i].x, xr[i].y, xr[i].z, xr[i].w};
            #pragma unroll
            for (int jj = 0; jj < 2; jj++) {
                const int p = i * 2 + jj;                 // kpair 0..7
                uint32_t lo, hi = hilo_pack(v[jj * 2], v[jj * 2 + 1], lo);
                const int reg = rbase + ((p >= 4) ? 2 : 0);
                const int ad  = fA_s * 128 + (lbase + (p & 3)) * 4 + reg;
                Ah[ad] = hi;
                Al[ad] = lo;
            }
        }
        // ---- stage B (prefetched uint4 -> linear store) ----
        ((uint4*)Bh)[tid] = bph;
        __syncthreads();

        // prefetch next chunk (x raw + B plane)
        if (t + 1 < NCHUNK) {
            #pragma unroll
            for (int i = 0; i < 4; i++)
                xr[i] = *(const float4*)(xrow + (t + 1) * 32 + i * 4);
            bph = *(const uint4*)(g_wbh + (t + 1) * 1024 + tid * 4);
        }

        // ---- compute: 2 k-steps x (8 nt x 2 passes) ----
        #pragma unroll
        for (int ks = 0; ks < 2; ks++) {
            const int fA = ks * 8 + warp;
            const uint4 AHv = *(const uint4*)(Ah + fA * 128 + lane * 4);
            const uint4 ALv = *(const uint4*)(Al + fA * 128 + lane * 4);
            uint2 BHv[8];
            #pragma unroll
            for (int nt = 0; nt < 8; nt++) {
                const int fB = ks * 8 + nt;
                BHv[nt] = *(const uint2*)(Bh + fB * 64 + lane * 2);
            }
            #pragma unroll
            for (int nt = 0; nt < 8; nt++) mma16(acc[nt], &AHv.x, &BHv[nt].x);
            #pragma unroll
            for (int nt = 0; nt < 8; nt++) mma16(acc[nt], &ALv.x, &BHv[nt].x);
        }
        __syncthreads();
    }

    // ---- dump logits (rescaled) to smem, pitch 65 ----
    float* L = (float*)dsmu;
    {
        const int row0 = warp * 16 + (lane >> 2);
        const int ec = (lane & 3) * 2;
        #pragma unroll
        for (int nt = 0; nt < 8; nt++) {
            const int e0 = nt * 8 + ec;
            L[row0 * 65 + e0]           = acc[nt][0] * RSCALE;
            L[row0 * 65 + e0 + 1]       = acc[nt][1] * RSCALE;
            L[(row0 + 8) * 65 + e0]     = acc[nt][2] * RSCALE;
            L[(row0 + 8) * 65 + e0 + 1] = acc[nt][3] * RSCALE;
        }
    }
    __syncthreads();

    // ---- per-token: top-4 scan, flag ambiguity, softmax (threads 0..127) ----
    float tv[4] = {-1e30f, -1e30f, -1e30f, -1e30f};
    int   tix[4] = {0, 0, 0, 0};
    bool  flag = false;
    if (tid < 128) {
        for (int e = 0; e < NE; e++) {
            const float Le = L[tid * 65 + e];
            if (Le > tv[3]) {
                int p = 3;
                while (p > 0 && Le > tv[p - 1]) {
                    tv[p] = tv[p - 1]; tix[p] = tix[p - 1]; p--;
                }
                tv[p] = Le; tix[p] = e;
            }
        }
        flag = (tv[0] - tv[1] < TAU) || (tv[1] - tv[2] < TAU);
        #pragma unroll
        for (int c = 0; c < 4; c++) cand[tid][c] = tix[c];

        float Z = 0.0f;
        const float mx = tv[0];
        #pragma unroll 8
        for (int e = 0; e < NE; e++) {
            const float pe = __expf(L[tid * 65 + e] - mx);
            Z += pe;
            L[tid * 65 + e] = pe;
        }
        rzs[tid] = 1.0f / Z;
    }
    __syncthreads();

    // ---- warp-cooperative exact fp32 recompute of flagged tokens ----
    if (warp < 4) {
        unsigned mask = __ballot_sync(0xffffffffu, flag);
        while (mask) {
            const int b = __ffs(mask) - 1; mask &= mask - 1;
            const int tk = warp * 32 + b;
            const float* xg = x + (size_t)(tok0 + tk) * HID;
            const int c0 = cand[tk][0], c1 = cand[tk][1],
                      c2 = cand[tk][2], c3 = cand[tk][3];
            float s0 = 0.f, s1 = 0.f, s2 = 0.f, s3 = 0.f;
            for (int k0 = lane * 4; k0 < HID; k0 += 128) {
                const float4 xa = *(const float4*)(xg + k0);
                const float4 w0 = *(const float4*)(w + (size_t)c0 * HID + k0);
                const float4 w1 = *(const float4*)(w + (size_t)c1 * HID + k0);
                const float4 w2 = *(const float4*)(w + (size_t)c2 * HID + k0);
                const float4 w3 = *(const float4*)(w + (size_t)c3 * HID + k0);
                s0 += xa.x*w0.x + xa.y*w0.y + xa.z*w0.z + xa.w*w0.w;
                s1 += xa.x*w1.x + xa.y*w1.y + xa.z*w1.z + xa.w*w1.w;
                s2 += xa.x*w2.x + xa.y*w2.y + xa.z*w2.z + xa.w*w2.w;
                s3 += xa.x*w3.x + xa.y*w3.y + xa.z*w3.z + xa.w*w3.w;
            }
            #pragma unroll
            for (int o = 16; o; o >>= 1) {
                s0 += __shfl_xor_sync(0xffffffffu, s0, o);
                s1 += __shfl_xor_sync(0xffffffffu, s1, o);
                s2 += __shfl_xor_sync(0xffffffffu, s2, o);
                s3 += __shfl_xor_sync(0xffffffffu, s3, o);
            }
            if (lane == 0) {
                evx[tk][0] = s0; evx[tk][1] = s1; evx[tk][2] = s2; evx[tk][3] = s3;
            }
        }
    }
    __syncthreads();

    // ---- finalize outputs (threads 0..127) ----
    if (tid < 128) {
        float ev[4];
        #pragma unroll
        for (int c = 0; c < 4; c++) ev[c] = flag ? evx[tid][c] : tv[c];

        int b1 = 0;
        #pragma unroll
        for (int c = 1; c < 4; c++)
            if (ev[c] > ev[b1] || (ev[c] == ev[b1] && tix[c] < tix[b1])) b1 = c;
        int b2 = (b1 == 0) ? 1 : 0;
        #pragma unroll
        for (int c = 0; c < 4; c++) {
            if (c == b1 || c == b2) continue;
            if (ev[c] > ev[b2] || (ev[c] == ev[b2] && tix[c] < tix[b2])) b2 = c;
        }

        const int gt = tok0 + tid;
        out[2 * gt + 0] = (float)tix[b1];
        out[2 * gt + 1] = (float)tix[b2];
        const float r = expf(ev[b2] - ev[b1]);
        const float inv = 1.0f / (1.0f + r);
        out[2 * NTOK + 2 * gt + 0] = inv;
        out[2 * NTOK + 2 * gt + 1] = r * inv;
        atomicAdd(&cnt_s[tix[b1]], 1);
        atomicAdd(&cnt_s[tix[b2]], 1);
    }
    __syncthreads();

    // ---- per-expert normalized-prob sums (all 256 threads) ----
    {
        const int e = tid & 63, h = tid >> 6;
        float s = 0.0f;
        float* L2 = (float*)dsmu;
        #pragma unroll 8
        for (int r2 = h * 32; r2 < h * 32 + 32; r2++) s += L2[r2 * 65 + e] * rzs[r2];
        psum[tid] = s;
    }
    __syncthreads();
    if (tid < NE) {
        const int b = tok0 >> 12;
        atomicAdd(&g_ssum[b * NE + tid],
                  psum[tid] + psum[64 + tid] + psum[128 + tid] + psum[192 + tid]);
        atomicAdd(&g_cnt[b * NE + tid], cnt_s[tid]);
    }
}

__global__ void aux_kernel(float* __restrict__ out) {
    int t = threadIdx.x;  // 256 = NBATCH*NE
    float v = ((float)g_cnt[t] * ((float)NE / (float)(SEQ * 2))) *
              (g_ssum[t] / (float)SEQ);
    #pragma unroll
    for (int o = 16; o; o >>= 1) v += __shfl_xor_sync(0xffffffffu, v, o);
    __shared__ float wsum[8];
    if ((t & 31) == 0) wsum[t >> 5] = v;
    __syncthreads();
    if (t < 8) {
        float s = wsum[t];
        #pragma unroll
        for (int o = 4; o; o >>= 1) s += __shfl_xor_sync(0xffu, s, o);
        if (t == 0) out[4 * NTOK] = 0.01f * s / (float)NBATCH;
    }
}

extern "C" void kernel_launch(void* const* d_in, const int* in_sizes, int n_in,
                              void* d_out, int out_size) {
    const float* x = (const float*)d_in[0];
    const float* w = (const float*)d_in[1];
    float* out = (float*)d_out;

    static int configured = 0;
    if (!configured) {
        cudaFuncSetAttribute(gate_kernel, cudaFuncAttributeMaxDynamicSharedMemorySize, DSM_BYTES);
        configured = 1;
    }
    wprep_kernel<<<NCHUNK, 256>>>(w);
    gate_kernel<<<NTOK / TTILE, 256, DSM_BYTES>>>(x, w, out);
    aux_kernel<<<1, 256>>>(out);
}

// round 17
// speedup vs baseline: 1.6723x; 1.4040x over previous
#include <cuda_runtime.h>
#include <cuda_fp16.h>
#include <cstdint>

#define NBATCH 4
#define SEQ    4096
#define HID    2048
#define NE     64
#define NTOK   (NBATCH * SEQ)   // 16384
#define TTILE  128
#define KC     32
#define NCHUNK (HID / KC)       // 64
#define TAU    1e-3f
#define WSCALE 64.0f
#define RSCALE (1.0f / 64.0f)

// dynamic smem bytes:
//  A buffers: 2 x (128 tokens x 128B) = 32768
//  B buffers: 2 x 4096 = 8192          -> total 40960
//  logits overlay after mainloop: 128*65*4 = 33280  (fits)
#define A_BUF_BYTES 16384
#define B_BASE      32768
#define B_BUF_BYTES 4096
#define DSM_BYTES   40960

__device__ uint32_t g_wbh[NCHUNK * 1024];   // w*64 hi fp16x2, fragment layout
__device__ float g_ssum[NBATCH * NE];
__device__ int   g_cnt [NBATCH * NE];

__device__ __forceinline__ void mma16(float* d, const uint32_t* a, const uint32_t* b) {
    asm volatile(
        "mma.sync.aligned.m16n8k16.row.col.f32.f16.f16.f32 "
        "{%0,%1,%2,%3}, {%4,%5,%6,%7}, {%8,%9}, {%0,%1,%2,%3};"
        : "+f"(d[0]), "+f"(d[1]), "+f"(d[2]), "+f"(d[3])
        : "r"(a[0]), "r"(a[1]), "r"(a[2]), "r"(a[3]), "r"(b[0]), "r"(b[1]));
}
__device__ __forceinline__ void ldm4(uint32_t* r, uint32_t addr) {
    asm volatile("ldmatrix.sync.aligned.m8n8.x4.shared.b16 {%0,%1,%2,%3}, [%4];"
                 : "=r"(r[0]), "=r"(r[1]), "=r"(r[2]), "=r"(r[3]) : "r"(addr));
}
__device__ __forceinline__ uint32_t smem_u32(const void* p) {
    return (uint32_t)__cvta_generic_to_shared(p);
}
__device__ __forceinline__ uint32_t hi_pack(float v0, float v1) {
    __half2 H = __halves2half2(__float2half_rn(v0), __float2half_rn(v1));
    return *(uint32_t*)&H;
}

// precompute w*64 hi fp16x2 in B-fragment layout (same as R16)
__global__ void wprep_kernel(const float* __restrict__ w) {
    const int t = blockIdx.x;
    if (t == 0 && threadIdx.x < NBATCH * NE) {
        g_ssum[threadIdx.x] = 0.0f; g_cnt[threadIdx.x] = 0;
    }
    #pragma unroll
    for (int it = 0; it < 4; it++) {
        const int idx = threadIdx.x + it * 256;
        const int r = idx & 1, l = (idx >> 1) & 31, fB = idx >> 6;
        const int nt = fB & 7, ks = fB >> 3;
        const int e = nt * 8 + (l >> 2);
        const int k = t * 32 + ks * 16 + ((l & 3) + r * 4) * 2;
        g_wbh[t * 1024 + idx] = hi_pack(w[(size_t)e * HID + k]     * WSCALE,
                                        w[(size_t)e * HID + k + 1] * WSCALE);
    }
}

extern __shared__ char dsmc[];

__global__ __launch_bounds__(256, 1)
void gate_kernel(const float* __restrict__ x, const float* __restrict__ w,
                 float* __restrict__ out)
{
    const int tid = threadIdx.x;
    const int lane = tid & 31, warp = tid >> 5;
    const int tok0 = blockIdx.x * TTILE;

    __shared__ int   cnt_s[NE];
    __shared__ float psum[256];
    __shared__ float rzs[128];
    __shared__ int   cand[128][4];
    __shared__ float evx[128][4];
    if (tid < NE) cnt_s[tid] = 0;

    const uint32_t sbase = smem_u32(dsmc);

    float acc[8][4];
    #pragma unroll
    for (int nt = 0; nt < 8; nt++)
        #pragma unroll
        for (int r = 0; r < 4; r++) acc[nt][r] = 0.0f;

    // staging coords: thread = token (tid>>1), k-half (tid&1) of each 32-k chunk
    const int tokr = tid >> 1, half = tid & 1;
    const float* xrow = x + (size_t)(tok0 + tokr) * HID + half * 16;
    const int sw = tokr & 7;
    const int offH0 = tokr * 128 + (((half * 2)     ^ sw) * 16);
    const int offH1 = tokr * 128 + (((half * 2 + 1) ^ sw) * 16);
    const int offL0 = tokr * 128 + (((half * 2 + 4) ^ sw) * 16);
    const int offL1 = tokr * 128 + (((half * 2 + 5) ^ sw) * 16);

    // compute coords: warp owns token tile warp*16; ldmatrix row per lane
    const int arow  = warp * 16 + (lane & 7) + ((lane >> 3) & 1) * 8;
    const int aroff = arow * 128;
    const int aswl  = lane & 7;
    const int kcl   = lane >> 4;            // 0..1

    float4 xr[4];
    uint4  bph;
    #pragma unroll
    for (int i = 0; i < 4; i++) xr[i] = *(const float4*)(xrow + i * 4);
    bph = *(const uint4*)(g_wbh + tid * 4);

    // stage chunk 0 into buf 0
    {
        char* ab = dsmc;
        uint32_t h[8], l[8];
        #pragma unroll
        for (int i = 0; i < 4; i++) {
            const float2 v0 = make_float2(xr[i].x, xr[i].y);
            const float2 v1 = make_float2(xr[i].z, xr[i].w);
            __half2 H0 = __float22half2_rn(v0), H1 = __float22half2_rn(v1);
            float2 f0 = __half22float2(H0), f1 = __half22float2(H1);
            __half2 L0 = __float22half2_rn(make_float2(v0.x - f0.x, v0.y - f0.y));
            __half2 L1 = __float22half2_rn(make_float2(v1.x - f1.x, v1.y - f1.y));
            h[i * 2] = *(uint32_t*)&H0; h[i * 2 + 1] = *(uint32_t*)&H1;
            l[i * 2] = *(uint32_t*)&L0; l[i * 2 + 1] = *(uint32_t*)&L1;
        }
        *(uint4*)(ab + offH0) = make_uint4(h[0], h[1], h[2], h[3]);
        *(uint4*)(ab + offH1) = make_uint4(h[4], h[5], h[6], h[7]);
        *(uint4*)(ab + offL0) = make_uint4(l[0], l[1], l[2], l[3]);
        *(uint4*)(ab + offL1) = make_uint4(l[4], l[5], l[6], l[7]);
        ((uint4*)(dsmc + B_BASE))[tid] = bph;
    }
    // load regs for chunk 1
    #pragma unroll
    for (int i = 0; i < 4; i++) xr[i] = *(const float4*)(xrow + 32 + i * 4);
    bph = *(const uint4*)(g_wbh + 1024 + tid * 4);
    __syncthreads();

    #pragma unroll 1
    for (int t = 0; t < NCHUNK; t++) {
        // ---- stage chunk t+1 into the idle buffer (overlaps HMMA below) ----
        if (t + 1 < NCHUNK) {
            char* ab = dsmc + ((t + 1) & 1) * A_BUF_BYTES;
            uint32_t h[8], l[8];
            #pragma unroll
            for (int i = 0; i < 4; i++) {
                const float2 v0 = make_float2(xr[i].x, xr[i].y);
                const float2 v1 = make_float2(xr[i].z, xr[i].w);
                __half2 H0 = __float22half2_rn(v0), H1 = __float22half2_rn(v1);
                float2 f0 = __half22float2(H0), f1 = __half22float2(H1);
                __half2 L0 = __float22half2_rn(make_float2(v0.x - f0.x, v0.y - f0.y));
                __half2 L1 = __float22half2_rn(make_float2(v1.x - f1.x, v1.y - f1.y));
                h[i * 2] = *(uint32_t*)&H0; h[i * 2 + 1] = *(uint32_t*)&H1;
                l[i * 2] = *(uint32_t*)&L0; l[i * 2 + 1] = *(uint32_t*)&L1;
            }
            *(uint4*)(ab + offH0) = make_uint4(h[0], h[1], h[2], h[3]);
            *(uint4*)(ab + offH1) = make_uint4(h[4], h[5], h[6], h[7]);
            *(uint4*)(ab + offL0) = make_uint4(l[0], l[1], l[2], l[3]);
            *(uint4*)(ab + offL1) = make_uint4(l[4], l[5], l[6], l[7]);
            ((uint4*)(dsmc + B_BASE + ((t + 1) & 1) * B_BUF_BYTES))[tid] = bph;
            // issue LDG for chunk t+2 (lands during the next iteration)
            if (t + 2 < NCHUNK) {
                #pragma unroll
                for (int i = 0; i < 4; i++)
                    xr[i] = *(const float4*)(xrow + (t + 2) * 32 + i * 4);
                bph = *(const uint4*)(g_wbh + (t + 2) * 1024 + tid * 4);
            }
        }

        // ---- compute chunk t from buf[t&1] ----
        {
            const uint32_t aB = sbase + (t & 1) * A_BUF_BYTES;
            const char* bB = dsmc + B_BASE + (t & 1) * B_BUF_BYTES;
            #pragma unroll
            for (int ks = 0; ks < 2; ks++) {
                const int kc = ks * 2 + kcl;
                uint32_t AH[4], AL[4];
                ldm4(AH, aB + aroff + ((kc       ^ aswl) * 16));
                ldm4(AL, aB + aroff + (((kc + 4) ^ aswl) * 16));
                uint2 BHv[8];
                #pragma unroll
                for (int nt = 0; nt < 8; nt++)
                    BHv[nt] = *(const uint2*)(bB + (ks * 8 + nt) * 256 + lane * 8);
                #pragma unroll
                for (int nt = 0; nt < 8; nt++) mma16(acc[nt], AH, &BHv[nt].x);
                #pragma unroll
                for (int nt = 0; nt < 8; nt++) mma16(acc[nt], AL, &BHv[nt].x);
            }
        }
        __syncthreads();
    }

    // ---- dump logits (rescaled) to smem, pitch 65 ----
    float* L = (float*)dsmc;
    {
        const int row0 = warp * 16 + (lane >> 2);
        const int ec = (lane & 3) * 2;
        #pragma unroll
        for (int nt = 0; nt < 8; nt++) {
            const int e0 = nt * 8 + ec;
            L[row0 * 65 + e0]           = acc[nt][0] * RSCALE;
            L[row0 * 65 + e0 + 1]       = acc[nt][1] * RSCALE;
            L[(row0 + 8) * 65 + e0]     = acc[nt][2] * RSCALE;
            L[(row0 + 8) * 65 + e0 + 1] = acc[nt][3] * RSCALE;
        }
    }
    __syncthreads();

    // ---- per-token: top-4 scan, flag ambiguity, softmax (threads 0..127) ----
    float tv[4] = {-1e30f, -1e30f, -1e30f, -1e30f};
    int   tix[4] = {0, 0, 0, 0};
    bool  flag = false;
    if (tid < 128) {
        for (int e = 0; e < NE; e++) {
            const float Le = L[tid * 65 + e];
            if (Le > tv[3]) {
                int p = 3;
                while (p > 0 && Le > tv[p - 1]) {
                    tv[p] = tv[p - 1]; tix[p] = tix[p - 1]; p--;
                }
                tv[p] = Le; tix[p] = e;
            }
        }
        flag = (tv[0] - tv[1] < TAU) || (tv[1] - tv[2] < TAU);
        #pragma unroll
        for (int c = 0; c < 4; c++) cand[tid][c] = tix[c];

        float Z = 0.0f;
        const float mx = tv[0];
        #pragma unroll 8
        for (int e = 0; e < NE; e++) {
            const float pe = __expf(L[tid * 65 + e] - mx);
            Z += pe;
            L[tid * 65 + e] = pe;
        }
        rzs[tid] = 1.0f / Z;
    }
    __syncthreads();

    // ---- warp-cooperative exact fp32 recompute of flagged tokens ----
    if (warp < 4) {
        unsigned mask = __ballot_sync(0xffffffffu, flag);
        while (mask) {
            const int b = __ffs(mask) - 1; mask &= mask - 1;
            const int tk = warp * 32 + b;
            const float* xg = x + (size_t)(tok0 + tk) * HID;
            const int c0 = cand[tk][0], c1 = cand[tk][1],
                      c2 = cand[tk][2], c3 = cand[tk][3];
            float s0 = 0.f, s1 = 0.f, s2 = 0.f, s3 = 0.f;
            for (int k0 = lane * 4; k0 < HID; k0 += 128) {
                const float4 xa = *(const float4*)(xg + k0);
                const float4 w0 = *(const float4*)(w + (size_t)c0 * HID + k0);
                const float4 w1 = *(const float4*)(w + (size_t)c1 * HID + k0);
                const float4 w2 = *(const float4*)(w + (size_t)c2 * HID + k0);
                const float4 w3 = *(const float4*)(w + (size_t)c3 * HID + k0);
                s0 += xa.x*w0.x + xa.y*w0.y + xa.z*w0.z + xa.w*w0.w;
                s1 += xa.x*w1.x + xa.y*w1.y + xa.z*w1.z + xa.w*w1.w;
                s2 += xa.x*w2.x + xa.y*w2.y + xa.z*w2.z + xa.w*w2.w;
                s3 += xa.x*w3.x + xa.y*w3.y + xa.z*w3.z + xa.w*w3.w;
            }
            #pragma unroll
            for (int o = 16; o; o >>= 1) {
                s0 += __shfl_xor_sync(0xffffffffu, s0, o);
                s1 += __shfl_xor_sync(0xffffffffu, s1, o);
                s2 += __shfl_xor_sync(0xffffffffu, s2, o);
                s3 += __shfl_xor_sync(0xffffffffu, s3, o);
            }
            if (lane == 0) {
                evx[tk][0] = s0; evx[tk][1] = s1; evx[tk][2] = s2; evx[tk][3] = s3;
            }
        }
    }
    __syncthreads();

    // ---- finalize outputs (threads 0..127) ----
    if (tid < 128) {
        float ev[4];
        #pragma unroll
        for (int c = 0; c < 4; c++) ev[c] = flag ? evx[tid][c] : tv[c];

        int b1 = 0;
        #pragma unroll
        for (int c = 1; c < 4; c++)
            if (ev[c] > ev[b1] || (ev[c] == ev[b1] && tix[c] < tix[b1])) b1 = c;
        int b2 = (b1 == 0) ? 1 : 0;
        #pragma unroll
        for (int c = 0; c < 4; c++) {
            if (c == b1 || c == b2) continue;
            if (ev[c] > ev[b2] || (ev[c] == ev[b2] && tix[c] < tix[b2])) b2 = c;
        }

        const int gt = tok0 + tid;
        out[2 * gt + 0] = (float)tix[b1];
        out[2 * gt + 1] = (float)tix[b2];
        const float r = expf(ev[b2] - ev[b1]);
        const float inv = 1.0f / (1.0f + r);
        out[2 * NTOK + 2 * gt + 0] = inv;
        out[2 * NTOK + 2 * gt + 1] = r * inv;
        atomicAdd(&cnt_s[tix[b1]], 1);
        atomicAdd(&cnt_s[tix[b2]], 1);
    }
    __syncthreads();

    // ---- per-expert normalized-prob sums (all 256 threads) ----
    {
        const int e = tid & 63, h = tid >> 6;
        float s = 0.0f;
        #pragma unroll 8
        for (int r2 = h * 32; r2 < h * 32 + 32; r2++) s += L[r2 * 65 + e] * rzs[r2];
        psum[tid] = s;
    }
    __syncthreads();
    if (tid < NE) {
        const int b = tok0 >> 12;
        atomicAdd(&g_ssum[b * NE + tid],
                  psum[tid] + psum[64 + tid] + psum[128 + tid] + psum[192 + tid]);
        atomicAdd(&g_cnt[b * NE + tid], cnt_s[tid]);
    }
}

__global__ void aux_kernel(float* __restrict__ out) {
    int t = threadIdx.x;  // 256 = NBATCH*NE
    float v = ((float)g_cnt[t] * ((float)NE / (float)(SEQ * 2))) *
              (g_ssum[t] / (float)SEQ);
    #pragma unroll
    for (int o = 16; o; o >>= 1) v += __shfl_xor_sync(0xffffffffu, v, o);
    __shared__ float wsum[8];
    if ((t & 31) == 0) wsum[t >> 5] = v;
    __syncthreads();
    if (t < 8) {
        float s = wsum[t];
        #pragma unroll
        for (int o = 4; o; o >>= 1) s += __shfl_xor_sync(0xffu, s, o);
        if (t == 0) out[4 * NTOK] = 0.01f * s / (float)NBATCH;
    }
}

extern "C" void kernel_launch(void* const* d_in, const int* in_sizes, int n_in,
                              void* d_out, int out_size) {
    const float* x = (const float*)d_in[0];
    const float* w = (const float*)d_in[1];
    float* out = (float*)d_out;

    static int configured = 0;
    if (!configured) {
        cudaFuncSetAttribute(gate_kernel, cudaFuncAttributeMaxDynamicSharedMemorySize, DSM_BYTES);
        configured = 1;
    }
    wprep_kernel<<<NCHUNK, 256>>>(w);
    gate_kernel<<<NTOK / TTILE, 256, DSM_BYTES>>>(x, w, out);
    aux_kernel<<<1, 256>>>(out);
}